// round 9
// baseline (speedup 1.0000x reference)
#include <cuda_runtime.h>

// DynamicRouting: N=64, C=4, H=W=256 fp32. Two kernels:
//   1) sum_kernel: per-(tensor,n,c) row sums -> g_sums[512]  (~24.5us, read cap)
//   2) main_kernel: redundant per-block gates hidden under input loads, dense
//      folded conv. SAMPLE ORDER REVERSED (n = 63 - blockIdx.y): early waves
//      read the x/y rows sum_kernel touched LAST, which are still L2-resident,
//      harvesting residue hits before the 201MB write stream churns L2.

#define HW   65536
#define HW4  16384
#define NSMP 64

__device__ float g_sums[512];   // [0..255]: x sums (n*4+c), [256..511]: y sums

// ---------------------------------------------------------------------------
// Pass 1: 512 blocks x 256 threads; block b sums one contiguous 64K-float row.
// Default caching: leaves the tail of its read stream resident in L2.
// ---------------------------------------------------------------------------
__global__ void __launch_bounds__(256)
sum_kernel(const float* __restrict__ x, const float* __restrict__ y) {
    int b = blockIdx.x;
    const float* base = (b < 256) ? (x + (size_t)b * HW)
                                  : (y + (size_t)(b - 256) * HW);
    const float4* src = (const float4*)base;

    float s0 = 0.f, s1 = 0.f, s2 = 0.f, s3 = 0.f;
    int t = threadIdx.x;
    for (int i = t; i < HW4; i += 1024) {
        float4 v0 = src[i];
        float4 v1 = src[i + 256];
        float4 v2 = src[i + 512];
        float4 v3 = src[i + 768];
        s0 += v0.x + v0.y + v0.z + v0.w;
        s1 += v1.x + v1.y + v1.z + v1.w;
        s2 += v2.x + v2.y + v2.z + v2.w;
        s3 += v3.x + v3.y + v3.z + v3.w;
    }
    float s = (s0 + s1) + (s2 + s3);

    #pragma unroll
    for (int o = 16; o > 0; o >>= 1)
        s += __shfl_down_sync(0xffffffffu, s, o);

    __shared__ float ws[8];
    if ((t & 31) == 0) ws[t >> 5] = s;
    __syncthreads();
    if (t < 8) {
        s = ws[t];
        #pragma unroll
        for (int o = 4; o > 0; o >>= 1)
            s += __shfl_down_sync(0xffu, s, o);
        if (t == 0) g_sums[b] = s;
    }
}

// ---------------------------------------------------------------------------
// Pass 2: grid (64,64), 256 thr, n REVERSED to match L2 residue recency.
// ---------------------------------------------------------------------------
__global__ void __launch_bounds__(256)
main_kernel(const float* __restrict__ x, const float* __restrict__ y,
            float* __restrict__ out,
            const float* __restrict__ w_rf1, const float* __restrict__ b_rf1,
            const float* __restrict__ w_rf2, const float* __restrict__ b_rf2,
            const float* __restrict__ w_e1,  const float* __restrict__ b_e1,
            const float* __restrict__ w_e2,  const float* __restrict__ b_e2,
            const float* __restrict__ w_e3,  const float* __restrict__ b_e3,
            const float* __restrict__ w_e4,  const float* __restrict__ b_e4) {
    const int n = 63 - blockIdx.y;        // <<< reversed sample order
    const int t = threadIdx.x;
    const int pid = blockIdx.x * 256 + t;

    const float4* xb = (const float4*)(x + (size_t)n * 4 * HW);
    const float4* yb = (const float4*)(y + (size_t)n * 4 * HW);

    // Bulk input loads FIRST (gate chain hides under them).
    float4 xv[4], yv[4];
    #pragma unroll
    for (int c = 0; c < 4; c++) {
        xv[c] = xb[(size_t)c * HW4 + pid];
        yv[c] = yb[(size_t)c * HW4 + pid];
    }

    // ---- Gates (redundant per block; g_sums is 2KB, L2-hot) ----
    __shared__ float mk[4];
    if (t == 0) {
        const float inv = 1.0f / (float)HW;
        float px[4], py[4];
        #pragma unroll
        for (int c = 0; c < 4; c++) {
            px[c] = g_sums[n * 4 + c] * inv;
            py[c] = g_sums[256 + n * 4 + c] * inv;
        }
        float gx1[2], gy1[2];
        #pragma unroll
        for (int j = 0; j < 2; j++) {
            float ax = b_rf1[j], ay = b_rf1[j];
            #pragma unroll
            for (int c = 0; c < 4; c++) {
                ax += px[c] * w_rf1[j * 4 + c];
                ay += py[c] * w_rf1[j * 4 + c];
            }
            gx1[j] = ax; gy1[j] = ay;
        }
        float gx[2], gy[2];
        #pragma unroll
        for (int i = 0; i < 2; i++) {
            float ax = b_rf2[i], ay = b_rf2[i];
            #pragma unroll
            for (int j = 0; j < 2; j++) {
                ax += gx1[j] * w_rf2[i * 2 + j];
                ay += gy1[j] * w_rf2[i * 2 + j];
            }
            gx[i] = ax; gy[i] = ay;
        }
        mk[0] = gx[0] > 0.f ? 1.f : 0.f;
        mk[1] = gx[1] > 0.f ? 1.f : 0.f;
        mk[2] = gy[0] > 0.f ? 1.f : 0.f;
        mk[3] = gy[1] > 0.f ? 1.f : 0.f;
    }
    __syncthreads();

    // ---- Fold masks + biases into effective coefficients (112 floats) ----
    __shared__ float cf[112];
    if (t < 112) {
        float v;
        if      (t < 16)  v = mk[0] * w_e1[t];
        else if (t < 32)  v = mk[2] * w_e3[t - 16];
        else if (t < 36)  v = mk[0] * b_e1[t - 32] + mk[2] * b_e3[t - 32];
        else if (t < 68)  v = mk[1] * w_e2[t - 36];
        else if (t < 100) v = mk[3] * w_e4[t - 68];
        else              v = mk[1] * b_e2[t - 100] + mk[3] * b_e4[t - 100];
        cf[t] = v;
    }
    __syncthreads();

    // ---- Dense pass: 4 out_x channels + 8 out_y channels ----
    float4* ox = (float4*)(out + (size_t)n * 4 * HW);
    #pragma unroll
    for (int o = 0; o < 4; o++) {
        float b = cf[32 + o];
        float4 acc = make_float4(b, b, b, b);
        #pragma unroll
        for (int c = 0; c < 4; c++) {
            float a1 = cf[o * 4 + c];
            float a2 = cf[16 + o * 4 + c];
            acc.x += a1 * xv[c].x + a2 * yv[c].x;
            acc.y += a1 * xv[c].y + a2 * yv[c].y;
            acc.z += a1 * xv[c].z + a2 * yv[c].z;
            acc.w += a1 * xv[c].w + a2 * yv[c].w;
        }
        __stcs(ox + (size_t)o * HW4 + pid, acc);
    }

    float4* oy = (float4*)(out + (size_t)NSMP * 4 * HW + (size_t)n * 8 * HW);
    #pragma unroll
    for (int o = 0; o < 8; o++) {
        float b = cf[100 + o];
        float4 acc = make_float4(b, b, b, b);
        #pragma unroll
        for (int c = 0; c < 4; c++) {
            float a1 = cf[36 + o * 4 + c];
            float a2 = cf[68 + o * 4 + c];
            acc.x += a1 * xv[c].x + a2 * yv[c].x;
            acc.y += a1 * xv[c].y + a2 * yv[c].y;
            acc.z += a1 * xv[c].z + a2 * yv[c].z;
            acc.w += a1 * xv[c].w + a2 * yv[c].w;
        }
        __stcs(oy + (size_t)o * HW4 + pid, acc);
    }
}

// ---------------------------------------------------------------------------
extern "C" void kernel_launch(void* const* d_in, const int* in_sizes, int n_in,
                              void* d_out, int out_size) {
    const float* x = (const float*)d_in[0];
    const float* y = (const float*)d_in[1];

    sum_kernel<<<512, 256>>>(x, y);

    dim3 grid(HW4 / 256, NSMP);
    main_kernel<<<grid, 256>>>(
        x, y, (float*)d_out,
        (const float*)d_in[2],  (const float*)d_in[3],
        (const float*)d_in[4],  (const float*)d_in[5],
        (const float*)d_in[6],  (const float*)d_in[7],
        (const float*)d_in[8],  (const float*)d_in[9],
        (const float*)d_in[10], (const float*)d_in[11],
        (const float*)d_in[12], (const float*)d_in[13]);
}

// round 10
// speedup vs baseline: 1.0097x; 1.0097x over previous
#include <cuda_runtime.h>

// DynamicRouting: N=64, C=4, H=W=256 fp32. Two kernels + PDL overlap:
//   1) sum_kernel: per-(tensor,n,c) row sums -> g_sums[512]  (~24.5us, DRAM cap)
//   2) main_kernel (Programmatic Dependent Launch): issues its independent bulk
//      input loads FIRST, then cudaGridDependencySynchronize() before reading
//      g_sums. Early main blocks overlap sum_kernel's tail, keeping DRAM
//      saturated across the kernel boundary.

#define HW   65536
#define HW4  16384
#define NSMP 64

__device__ float g_sums[512];   // [0..255]: x sums (n*4+c), [256..511]: y sums

// ---------------------------------------------------------------------------
// Pass 1: 512 blocks x 256 threads; block b sums one contiguous 64K-float row.
// ---------------------------------------------------------------------------
__global__ void __launch_bounds__(256)
sum_kernel(const float* __restrict__ x, const float* __restrict__ y) {
    int b = blockIdx.x;
    const float* base = (b < 256) ? (x + (size_t)b * HW)
                                  : (y + (size_t)(b - 256) * HW);
    const float4* src = (const float4*)base;

    float s0 = 0.f, s1 = 0.f, s2 = 0.f, s3 = 0.f;
    int t = threadIdx.x;
    for (int i = t; i < HW4; i += 1024) {
        float4 v0 = src[i];
        float4 v1 = src[i + 256];
        float4 v2 = src[i + 512];
        float4 v3 = src[i + 768];
        s0 += v0.x + v0.y + v0.z + v0.w;
        s1 += v1.x + v1.y + v1.z + v1.w;
        s2 += v2.x + v2.y + v2.z + v2.w;
        s3 += v3.x + v3.y + v3.z + v3.w;
    }
    float s = (s0 + s1) + (s2 + s3);

    #pragma unroll
    for (int o = 16; o > 0; o >>= 1)
        s += __shfl_down_sync(0xffffffffu, s, o);

    __shared__ float ws[8];
    if ((t & 31) == 0) ws[t >> 5] = s;
    __syncthreads();
    if (t < 8) {
        s = ws[t];
        #pragma unroll
        for (int o = 4; o > 0; o >>= 1)
            s += __shfl_down_sync(0xffu, s, o);
        if (t == 0) g_sums[b] = s;
    }
}

// ---------------------------------------------------------------------------
// Pass 2: grid (64,64), 256 thr. PDL secondary: independent input loads are
// issued BEFORE cudaGridDependencySynchronize(); gates + dense pass after.
// ---------------------------------------------------------------------------
__global__ void __launch_bounds__(256)
main_kernel(const float* __restrict__ x, const float* __restrict__ y,
            float* __restrict__ out,
            const float* __restrict__ w_rf1, const float* __restrict__ b_rf1,
            const float* __restrict__ w_rf2, const float* __restrict__ b_rf2,
            const float* __restrict__ w_e1,  const float* __restrict__ b_e1,
            const float* __restrict__ w_e2,  const float* __restrict__ b_e2,
            const float* __restrict__ w_e3,  const float* __restrict__ b_e3,
            const float* __restrict__ w_e4,  const float* __restrict__ b_e4) {
    const int n = blockIdx.y;
    const int t = threadIdx.x;
    const int pid = blockIdx.x * 256 + t;

    const float4* xb = (const float4*)(x + (size_t)n * 4 * HW);
    const float4* yb = (const float4*)(y + (size_t)n * 4 * HW);

    // Independent bulk loads FIRST — overlap with sum_kernel's tail under PDL.
    float4 xv[4], yv[4];
    #pragma unroll
    for (int c = 0; c < 4; c++) {
        xv[c] = xb[(size_t)c * HW4 + pid];
        yv[c] = yb[(size_t)c * HW4 + pid];
    }

    // Wait for upstream grid (sum_kernel) before touching g_sums.
    cudaGridDependencySynchronize();

    // ---- Gates (redundant per block; g_sums is 2KB, L2-hot) ----
    __shared__ float mk[4];
    if (t == 0) {
        const float inv = 1.0f / (float)HW;
        float px[4], py[4];
        #pragma unroll
        for (int c = 0; c < 4; c++) {
            px[c] = g_sums[n * 4 + c] * inv;
            py[c] = g_sums[256 + n * 4 + c] * inv;
        }
        float gx1[2], gy1[2];
        #pragma unroll
        for (int j = 0; j < 2; j++) {
            float ax = b_rf1[j], ay = b_rf1[j];
            #pragma unroll
            for (int c = 0; c < 4; c++) {
                ax += px[c] * w_rf1[j * 4 + c];
                ay += py[c] * w_rf1[j * 4 + c];
            }
            gx1[j] = ax; gy1[j] = ay;
        }
        float gx[2], gy[2];
        #pragma unroll
        for (int i = 0; i < 2; i++) {
            float ax = b_rf2[i], ay = b_rf2[i];
            #pragma unroll
            for (int j = 0; j < 2; j++) {
                ax += gx1[j] * w_rf2[i * 2 + j];
                ay += gy1[j] * w_rf2[i * 2 + j];
            }
            gx[i] = ax; gy[i] = ay;
        }
        mk[0] = gx[0] > 0.f ? 1.f : 0.f;
        mk[1] = gx[1] > 0.f ? 1.f : 0.f;
        mk[2] = gy[0] > 0.f ? 1.f : 0.f;
        mk[3] = gy[1] > 0.f ? 1.f : 0.f;
    }
    __syncthreads();

    // ---- Fold masks + biases into effective coefficients (112 floats) ----
    __shared__ float cf[112];
    if (t < 112) {
        float v;
        if      (t < 16)  v = mk[0] * w_e1[t];
        else if (t < 32)  v = mk[2] * w_e3[t - 16];
        else if (t < 36)  v = mk[0] * b_e1[t - 32] + mk[2] * b_e3[t - 32];
        else if (t < 68)  v = mk[1] * w_e2[t - 36];
        else if (t < 100) v = mk[3] * w_e4[t - 68];
        else              v = mk[1] * b_e2[t - 100] + mk[3] * b_e4[t - 100];
        cf[t] = v;
    }
    __syncthreads();

    // ---- Dense pass: 4 out_x channels + 8 out_y channels ----
    float4* ox = (float4*)(out + (size_t)n * 4 * HW);
    #pragma unroll
    for (int o = 0; o < 4; o++) {
        float b = cf[32 + o];
        float4 acc = make_float4(b, b, b, b);
        #pragma unroll
        for (int c = 0; c < 4; c++) {
            float a1 = cf[o * 4 + c];
            float a2 = cf[16 + o * 4 + c];
            acc.x += a1 * xv[c].x + a2 * yv[c].x;
            acc.y += a1 * xv[c].y + a2 * yv[c].y;
            acc.z += a1 * xv[c].z + a2 * yv[c].z;
            acc.w += a1 * xv[c].w + a2 * yv[c].w;
        }
        __stcs(ox + (size_t)o * HW4 + pid, acc);
    }

    float4* oy = (float4*)(out + (size_t)NSMP * 4 * HW + (size_t)n * 8 * HW);
    #pragma unroll
    for (int o = 0; o < 8; o++) {
        float b = cf[100 + o];
        float4 acc = make_float4(b, b, b, b);
        #pragma unroll
        for (int c = 0; c < 4; c++) {
            float a1 = cf[36 + o * 4 + c];
            float a2 = cf[68 + o * 4 + c];
            acc.x += a1 * xv[c].x + a2 * yv[c].x;
            acc.y += a1 * xv[c].y + a2 * yv[c].y;
            acc.z += a1 * xv[c].z + a2 * yv[c].z;
            acc.w += a1 * xv[c].w + a2 * yv[c].w;
        }
        __stcs(oy + (size_t)o * HW4 + pid, acc);
    }
}

// ---------------------------------------------------------------------------
extern "C" void kernel_launch(void* const* d_in, const int* in_sizes, int n_in,
                              void* d_out, int out_size) {
    const float* x = (const float*)d_in[0];
    const float* y = (const float*)d_in[1];

    sum_kernel<<<512, 256>>>(x, y);

    // main_kernel as PDL secondary: may begin launching while sum_kernel runs;
    // correctness enforced by cudaGridDependencySynchronize() in the kernel.
    cudaLaunchConfig_t cfg = {};
    cfg.gridDim  = dim3(HW4 / 256, NSMP);
    cfg.blockDim = dim3(256);
    cfg.dynamicSmemBytes = 0;
    cfg.stream = 0;   // legacy default stream (same as <<<>>> above)
    cudaLaunchAttribute attrs[1];
    attrs[0].id = cudaLaunchAttributeProgrammaticStreamSerialization;
    attrs[0].val.programmaticStreamSerializationAllowed = 1;
    cfg.attrs = attrs;
    cfg.numAttrs = 1;

    cudaLaunchKernelEx(&cfg, main_kernel,
        x, y, (float*)d_out,
        (const float*)d_in[2],  (const float*)d_in[3],
        (const float*)d_in[4],  (const float*)d_in[5],
        (const float*)d_in[6],  (const float*)d_in[7],
        (const float*)d_in[8],  (const float*)d_in[9],
        (const float*)d_in[10], (const float*)d_in[11],
        (const float*)d_in[12], (const float*)d_in[13]);
}